// round 8
// baseline (speedup 1.0000x reference)
#include <cuda_runtime.h>
#include <cuda_bf16.h>
#include <cstdint>

#define N_NODES 100000
#define EMB_DIM 128
#define HIDDEN  64
#define N_EDGES 1600000
#define TILE_M  128
#define N_TILES ((N_NODES + TILE_M - 1) / TILE_M)   // 782

// Scratch: per-node precomputed [u | v], 128 floats per node (51.2 MB).
__device__ float g_UV[(size_t)N_NODES * 128];
// 1 if edge_index is int64 on device, 0 if int32.
__device__ int g_idx_is_64;

// ---- smem layout for kernel 1 (bf16 tiles, 272B row stride, 16B-aligned rows)
#define ROW_BYTES 272                      // 128 bf16 (256B) + 16B pad
#define TILE_BYTES (128 * ROW_BYTES)       // 34816
#define SM_A_HI 0
#define SM_A_LO (SM_A_HI + TILE_BYTES)
#define SM_B_HI (SM_A_LO + TILE_BYTES)
#define SM_B_LO (SM_B_HI + TILE_BYTES)
#define SMEM_TOTAL (4 * TILE_BYTES)        // 139264 B

__device__ __forceinline__ uint32_t smem_u32(const void* p) {
    uint32_t a;
    asm("{ .reg .u64 t; cvta.to.shared.u64 t, %1; cvt.u32.u64 %0, t; }"
        : "=r"(a) : "l"(p));
    return a;
}

#define LDSM_X4(r0, r1, r2, r3, addr) \
    asm volatile("ldmatrix.sync.aligned.m8n8.x4.shared.b16 {%0,%1,%2,%3}, [%4];" \
        : "=r"(r0), "=r"(r1), "=r"(r2), "=r"(r3) : "r"(addr))

__device__ __forceinline__ void mma_bf16(float* d, uint32_t a0, uint32_t a1,
                                         uint32_t a2, uint32_t a3,
                                         uint32_t b0, uint32_t b1) {
    asm volatile(
        "mma.sync.aligned.m16n8k16.row.col.f32.bf16.bf16.f32 "
        "{%0,%1,%2,%3}, {%4,%5,%6,%7}, {%8,%9}, {%0,%1,%2,%3};"
        : "+f"(d[0]), "+f"(d[1]), "+f"(d[2]), "+f"(d[3])
        : "r"(a0), "r"(a1), "r"(a2), "r"(a3), "r"(b0), "r"(b1));
}

// ---------------------------------------------------------------------------
// Kernel 1 (warp-MMA): per 128-node tile, UV[m][n] = sum_k emb[m][k]*Wc[k][n]
//   Wc[k][n] = W1[k][n] (n<64) | W1[128+k][n-64] (n>=64)
// Split-bf16 3 passes: Ahi*Bhi + Ahi*Blo + Alo*Bhi, fp32 register accums.
// 8 warps; warp w computes rows [16w,16w+16) x all 128 cols.
// B staged transposed (coalesced GLOBAL reads, scattered smem writes):
//   Wt[n][k] = Wc[k][n], k contiguous -> the mma "col" operand layout.
// All fragments loaded via ldmatrix.x4. Block 0 also detects eidx dtype.
// ---------------------------------------------------------------------------
__global__ __launch_bounds__(256)
void precompute_uv_mma(const float* __restrict__ emb,
                       const float* __restrict__ W1,
                       const int* __restrict__ eidx32) {
    extern __shared__ char smem[];
    int tid = threadIdx.x;

    // --- dtype detection (block 0): int64 indices < 2^31 have zero odd words
    __shared__ int s_any;
    if (blockIdx.x == 0) {
        if (tid == 0) s_any = 0;
        __syncthreads();
        if (tid < 128) {
            int w = eidx32[2 * (tid * 37 + 1) + 1];
            if (w != 0) atomicOr(&s_any, 1);
        }
        __syncthreads();
        if (tid == 0) g_idx_is_64 = (s_any == 0) ? 1 : 0;
    }

    int base = blockIdx.x * TILE_M;

    // --- stage A (emb tile) hi/lo: coalesced float2 reads, row-major smem
    for (int i = tid; i < 128 * 64; i += 256) {
        int row = i >> 6;
        int kk = (i & 63) * 2;
        int node = base + row;
        float2 x = (node < N_NODES)
                 ? *(const float2*)(emb + (size_t)node * EMB_DIM + kk)
                 : make_float2(0.f, 0.f);
        __nv_bfloat162 h, l;
        h.x = __float2bfloat16(x.x); h.y = __float2bfloat16(x.y);
        l.x = __float2bfloat16(x.x - __bfloat162float(h.x));
        l.y = __float2bfloat16(x.y - __bfloat162float(h.y));
        *(__nv_bfloat162*)(smem + SM_A_HI + row * ROW_BYTES + kk * 2) = h;
        *(__nv_bfloat162*)(smem + SM_A_LO + row * ROW_BYTES + kk * 2) = l;
    }

    // --- stage B hi/lo: COALESCED read of W1 [256*64], transpose on STS side
    //   W1 row r, col c  ->  k = r % 128, n = c + 64*(r >= 128)
    for (int i = tid; i < 128 * 64; i += 256) {   // 8192 float2 = 16384 floats
        float2 x = *(const float2*)(W1 + 2 * (size_t)i);
        int r = (2 * i) >> 6;        // W1 row (0..255)
        int c = (2 * i) & 63;        // W1 col (even)
        int k = r & 127;
        int n = c + ((r >> 7) << 6);
        __nv_bfloat16 h0 = __float2bfloat16(x.x);
        __nv_bfloat16 h1 = __float2bfloat16(x.y);
        char* bh = smem + SM_B_HI + n * ROW_BYTES + k * 2;
        char* bl = smem + SM_B_LO + n * ROW_BYTES + k * 2;
        *(__nv_bfloat16*)(bh)                 = h0;
        *(__nv_bfloat16*)(bh + ROW_BYTES)     = h1;   // n+1, same k
        *(__nv_bfloat16*)(bl)             = __float2bfloat16(x.x - __bfloat162float(h0));
        *(__nv_bfloat16*)(bl + ROW_BYTES) = __float2bfloat16(x.y - __bfloat162float(h1));
    }
    __syncthreads();

    int wid = tid >> 5, lane = tid & 31;
    int g = lane >> 2, t = lane & 3;
    int m0 = wid * 16;

    // ldmatrix per-lane address offsets (bytes, within a tile)
    // A (x4): M0 rows m0+l @k0 | M1 rows m0+8+l @k0 | M2 rows m0+l @k0+8 | M3 ...
    uint32_t a_off = (uint32_t)((m0 + (lane & 7) + (((lane >> 3) & 1) << 3)) * ROW_BYTES
                                + ((lane >> 4) << 4));
    // B (x4): M0 rows n0+l @k0 | M1 rows n0+l @k0+8 | M2 rows n0+8+l @k0 | M3 ...
    uint32_t b_off = (uint32_t)(((lane & 7) + ((lane >> 4) << 3)) * ROW_BYTES
                                + (((lane >> 3) & 1) << 4));

    uint32_t sb = smem_u32(smem);

    float acc[16][4];
    #pragma unroll
    for (int j = 0; j < 16; j++)
        acc[j][0] = acc[j][1] = acc[j][2] = acc[j][3] = 0.f;

    const int a_sel[3] = {SM_A_HI, SM_A_HI, SM_A_LO};
    const int b_sel[3] = {SM_B_HI, SM_B_LO, SM_B_HI};

    for (int p = 0; p < 3; p++) {
        uint32_t A_base = sb + a_sel[p] + a_off;
        uint32_t B_base = sb + b_sel[p] + b_off;
        #pragma unroll
        for (int ks = 0; ks < 8; ks++) {
            uint32_t kadd = (uint32_t)(ks * 32);   // 16 bf16 = 32 B per k-step
            uint32_t a0, a1, a2, a3;
            LDSM_X4(a0, a1, a2, a3, A_base + kadd);
            #pragma unroll
            for (int jj = 0; jj < 8; jj++) {
                uint32_t b0, b1, b2, b3;   // two n-tiles: 16jj.. and 16jj+8..
                LDSM_X4(b0, b1, b2, b3, B_base + kadd + (uint32_t)(jj * 16 * ROW_BYTES));
                mma_bf16(acc[2 * jj],     a0, a1, a2, a3, b0, b1);
                mma_bf16(acc[2 * jj + 1], a0, a1, a2, a3, b2, b3);
            }
        }
    }

    // --- write out: lane owns D[g][2t..2t+1] and D[g+8][2t..2t+1] per n-tile
    int node0 = base + m0 + g;
    int node1 = base + m0 + 8 + g;
    #pragma unroll
    for (int j = 0; j < 16; j++) {
        int col = 8 * j + 2 * t;
        if (node0 < N_NODES)
            *(float2*)(g_UV + (size_t)node0 * 128 + col) = make_float2(acc[j][0], acc[j][1]);
        if (node1 < N_NODES)
            *(float2*)(g_UV + (size_t)node1 * 128 + col) = make_float2(acc[j][2], acc[j][3]);
    }
}

// ---------------------------------------------------------------------------
// Kernel 2: per-edge score (unchanged R5 winner).
// 8 lanes per edge; lane s owns cols {4s..4s+3, 32+4s..32+4s+3} so every
// LDG.128's 8-lane group covers exactly one contiguous 128B line.
// ---------------------------------------------------------------------------
__global__ __launch_bounds__(256)
void edge_score_kernel(const void* __restrict__ eidx_raw,
                       const float* __restrict__ b1,
                       const float* __restrict__ W2,
                       const float* __restrict__ b2,
                       float* __restrict__ out) {
    __shared__ float sb1[64];
    __shared__ float sw2[64];
    __shared__ float sb2;
    if (threadIdx.x < 64) {
        sb1[threadIdx.x] = b1[threadIdx.x];
        sw2[threadIdx.x] = W2[threadIdx.x];
    }
    if (threadIdx.x == 0) sb2 = b2[0];
    __syncthreads();

    int gtid = blockIdx.x * blockDim.x + threadIdx.x;
    int e = gtid >> 3;
    if (e >= N_EDGES) return;
    int s = threadIdx.x & 7;

    long long src, tgt;
    if (g_idx_is_64) {
        const long long* eidx = (const long long*)eidx_raw;
        src = eidx[e];
        tgt = eidx[N_EDGES + e];
    } else {
        const int* eidx = (const int*)eidx_raw;
        src = eidx[e];
        tgt = eidx[N_EDGES + e];
    }

    const float4* urow = (const float4*)(g_UV + (size_t)src * 128);
    const float4* vrow = (const float4*)(g_UV + (size_t)tgt * 128) + 16;
    float4 u0 = urow[s];
    float4 u1 = urow[8 + s];
    float4 v0 = vrow[s];
    float4 v1 = vrow[8 + s];

    float4 bb0 = *(const float4*)(sb1 + s * 4);
    float4 bb1 = *(const float4*)(sb1 + 32 + s * 4);
    float4 w0  = *(const float4*)(sw2 + s * 4);
    float4 w1  = *(const float4*)(sw2 + 32 + s * 4);

    float p = 0.f;
    {
        float z;
        z = fmaxf(u0.x + v0.x + bb0.x, 0.f); p = fmaf(z, w0.x, p);
        z = fmaxf(u0.y + v0.y + bb0.y, 0.f); p = fmaf(z, w0.y, p);
        z = fmaxf(u0.z + v0.z + bb0.z, 0.f); p = fmaf(z, w0.z, p);
        z = fmaxf(u0.w + v0.w + bb0.w, 0.f); p = fmaf(z, w0.w, p);
        z = fmaxf(u1.x + v1.x + bb1.x, 0.f); p = fmaf(z, w1.x, p);
        z = fmaxf(u1.y + v1.y + bb1.y, 0.f); p = fmaf(z, w1.y, p);
        z = fmaxf(u1.z + v1.z + bb1.z, 0.f); p = fmaf(z, w1.z, p);
        z = fmaxf(u1.w + v1.w + bb1.w, 0.f); p = fmaf(z, w1.w, p);
    }

    p += __shfl_xor_sync(0xFFFFFFFFu, p, 4);
    p += __shfl_xor_sync(0xFFFFFFFFu, p, 2);
    p += __shfl_xor_sync(0xFFFFFFFFu, p, 1);

    if (s == 0) out[e] = p + sb2;
}

// ---------------------------------------------------------------------------
extern "C" void kernel_launch(void* const* d_in, const int* in_sizes, int n_in,
                              void* d_out, int out_size) {
    const float* emb  = (const float*)d_in[0];
    const void*  eidx = d_in[1];
    const float* W1   = (const float*)d_in[2];
    const float* b1   = (const float*)d_in[3];
    const float* W2   = (const float*)d_in[4];
    const float* b2   = (const float*)d_in[5];
    float*       out  = (float*)d_out;

    cudaFuncSetAttribute(precompute_uv_mma,
                         cudaFuncAttributeMaxDynamicSharedMemorySize, SMEM_TOTAL);

    // Kernel 1: 782 CTAs, one 128-node tile each (block 0 also detects dtype)
    precompute_uv_mma<<<N_TILES, 256, SMEM_TOTAL>>>(emb, W1, (const int*)eidx);

    // Kernel 2: 8 threads per edge
    {
        long long threads = (long long)N_EDGES * 8;
        int blocks = (int)((threads + 255) / 256);
        edge_score_kernel<<<blocks, 256>>>(eidx, b1, W2, b2, out);
    }
}

// round 9
// speedup vs baseline: 1.4619x; 1.4619x over previous
#include <cuda_runtime.h>
#include <cuda_bf16.h>
#include <cuda_fp16.h>
#include <cstdint>

#define N_NODES 100000
#define EMB_DIM 128
#define HIDDEN  64
#define N_EDGES 1600000

// Scratch: per-node precomputed [u | v] in fp16, 128 halves = 256 B per node
// (25.6 MB total; u = cols 0..63 -> one 128B line, v = cols 64..127 -> one line)
__device__ __half g_UVh[(size_t)N_NODES * 128];
// 1 if edge_index is int64 on device, 0 if int32.
__device__ int g_idx_is_64;

// ---------------------------------------------------------------------------
// Kernel 1: UV[n][j] = sum_k emb[n][k] * Wc[k][j]   (fp32 math, fp16 store)
//   Wc[k][j] = W1[k][j]        for j <  64   (u half)
//   Wc[k][j] = W1[128+k][j-64] for j >= 64   (v half)
// One warp computes 8 nodes; lane owns 4 output cols (4*lane .. 4*lane+3).
// Wc (128x128 fp32 = 64 KB) staged in dynamic shared memory per block.
// Block 0 additionally detects the edge_index dtype (int32 vs int64).
// ---------------------------------------------------------------------------
extern __shared__ float sW[];  // 128*128 floats

__global__ __launch_bounds__(256)
void precompute_uv_kernel(const float* __restrict__ emb,
                          const float* __restrict__ W1,
                          const int* __restrict__ eidx32) {
    // --- dtype detection (block 0 only): if int64 with values < 2^31,
    // every odd 32-bit word is 0. Sample 128 odd-word positions. ---
    __shared__ int s_any;
    if (blockIdx.x == 0) {
        if (threadIdx.x == 0) s_any = 0;
        __syncthreads();
        if (threadIdx.x < 128) {
            int w = eidx32[2 * ((int)threadIdx.x * 37 + 1) + 1];
            if (w != 0) atomicOr(&s_any, 1);
        }
        __syncthreads();
        if (threadIdx.x == 0) g_idx_is_64 = (s_any == 0) ? 1 : 0;
    }

    // --- stage Wc into shared: W1 [256,64] row-major -> Wc [128,128] ---
    for (int i = threadIdx.x; i < 128 * 64; i += blockDim.x) {
        int k = i >> 6;          // 0..127
        int h = i & 63;          // 0..63
        sW[k * 128 + h]      = W1[k * 64 + h];
        sW[k * 128 + 64 + h] = W1[(128 + k) * 64 + h];
    }
    __syncthreads();

    int warp = (blockIdx.x * blockDim.x + threadIdx.x) >> 5;
    int lane = threadIdx.x & 31;
    int node0 = warp * 8;
    if (node0 >= N_NODES) return;

    float4 acc[8];
    #pragma unroll
    for (int n = 0; n < 8; n++) acc[n] = make_float4(0.f, 0.f, 0.f, 0.f);

    const float* embp = emb + (size_t)node0 * EMB_DIM;

    #pragma unroll 4
    for (int kc = 0; kc < 128; kc += 4) {
        float4 e[8];
        #pragma unroll
        for (int n = 0; n < 8; n++)
            e[n] = *(const float4*)(embp + n * EMB_DIM + kc);

        #pragma unroll
        for (int kk = 0; kk < 4; kk++) {
            float4 w = *(const float4*)(&sW[(kc + kk) * 128 + lane * 4]);
            #pragma unroll
            for (int n = 0; n < 8; n++) {
                float ev = (kk == 0) ? e[n].x : (kk == 1) ? e[n].y
                         : (kk == 2) ? e[n].z : e[n].w;
                acc[n].x = fmaf(ev, w.x, acc[n].x);
                acc[n].y = fmaf(ev, w.y, acc[n].y);
                acc[n].z = fmaf(ev, w.z, acc[n].z);
                acc[n].w = fmaf(ev, w.w, acc[n].w);
            }
        }
    }

    // fp16 store: 4 cols per lane = 2 half2 = 8 B
    #pragma unroll
    for (int n = 0; n < 8; n++) {
        __half2 h0 = __floats2half2_rn(acc[n].x, acc[n].y);
        __half2 h1 = __floats2half2_rn(acc[n].z, acc[n].w);
        uint2 packed;
        packed.x = *(uint32_t*)&h0;
        packed.y = *(uint32_t*)&h1;
        *(uint2*)(g_UVh + (size_t)(node0 + n) * 128 + lane * 4) = packed;
    }
}

// ---------------------------------------------------------------------------
// Kernel 2: per-edge score.
// 8 lanes per edge (4 edges/warp). Lane s owns cols 8s..8s+7 (8 halves = 16B).
// The 8-lane group's uint4 loads cover exactly ONE 128B line per gather:
//   u = row[s], v = row[8+s]  -> 2 lines/edge total (was 4 with fp32 UV).
//   z = relu(u[src] + v[tgt] + b1);  score = z . W2 + b2   (fp32 math)
// ---------------------------------------------------------------------------
__global__ __launch_bounds__(256)
void edge_score_kernel(const void* __restrict__ eidx_raw,
                       const float* __restrict__ b1,
                       const float* __restrict__ W2,
                       const float* __restrict__ b2,
                       float* __restrict__ out) {
    __shared__ float sb1[64];
    __shared__ float sw2[64];
    __shared__ float sb2;
    if (threadIdx.x < 64) {
        sb1[threadIdx.x] = b1[threadIdx.x];
        sw2[threadIdx.x] = W2[threadIdx.x];
    }
    if (threadIdx.x == 0) sb2 = b2[0];
    __syncthreads();

    int gtid = blockIdx.x * blockDim.x + threadIdx.x;
    int e = gtid >> 3;
    if (e >= N_EDGES) return;
    int s = threadIdx.x & 7;

    long long src, tgt;
    if (g_idx_is_64) {
        const long long* eidx = (const long long*)eidx_raw;
        src = eidx[e];
        tgt = eidx[N_EDGES + e];
    } else {
        const int* eidx = (const int*)eidx_raw;
        src = eidx[e];
        tgt = eidx[N_EDGES + e];
    }

    // u chunk: halves 8s..8s+7 of src row;  v chunk: halves 64+8s.. of tgt row
    uint4 uraw = *((const uint4*)(g_UVh + (size_t)src * 128) + s);
    uint4 vraw = *((const uint4*)(g_UVh + (size_t)tgt * 128) + 8 + s);

    const __half2* up = (const __half2*)&uraw;
    const __half2* vp = (const __half2*)&vraw;

    float4 bb0 = *(const float4*)(sb1 + s * 8);
    float4 bb1 = *(const float4*)(sb1 + s * 8 + 4);
    float4 w0  = *(const float4*)(sw2 + s * 8);
    float4 w1  = *(const float4*)(sw2 + s * 8 + 4);

    float2 u01 = __half22float2(up[0]);
    float2 u23 = __half22float2(up[1]);
    float2 u45 = __half22float2(up[2]);
    float2 u67 = __half22float2(up[3]);
    float2 v01 = __half22float2(vp[0]);
    float2 v23 = __half22float2(vp[1]);
    float2 v45 = __half22float2(vp[2]);
    float2 v67 = __half22float2(vp[3]);

    float p = 0.f;
    {
        float z;
        z = fmaxf(u01.x + v01.x + bb0.x, 0.f); p = fmaf(z, w0.x, p);
        z = fmaxf(u01.y + v01.y + bb0.y, 0.f); p = fmaf(z, w0.y, p);
        z = fmaxf(u23.x + v23.x + bb0.z, 0.f); p = fmaf(z, w0.z, p);
        z = fmaxf(u23.y + v23.y + bb0.w, 0.f); p = fmaf(z, w0.w, p);
        z = fmaxf(u45.x + v45.x + bb1.x, 0.f); p = fmaf(z, w1.x, p);
        z = fmaxf(u45.y + v45.y + bb1.y, 0.f); p = fmaf(z, w1.y, p);
        z = fmaxf(u67.x + v67.x + bb1.z, 0.f); p = fmaf(z, w1.z, p);
        z = fmaxf(u67.y + v67.y + bb1.w, 0.f); p = fmaf(z, w1.w, p);
    }

    // reduce over the 8-lane group
    p += __shfl_xor_sync(0xFFFFFFFFu, p, 4);
    p += __shfl_xor_sync(0xFFFFFFFFu, p, 2);
    p += __shfl_xor_sync(0xFFFFFFFFu, p, 1);

    if (s == 0) out[e] = p + sb2;
}

// ---------------------------------------------------------------------------
extern "C" void kernel_launch(void* const* d_in, const int* in_sizes, int n_in,
                              void* d_out, int out_size) {
    const float* emb  = (const float*)d_in[0];
    const void*  eidx = d_in[1];
    const float* W1   = (const float*)d_in[2];
    const float* b1   = (const float*)d_in[3];
    const float* W2   = (const float*)d_in[4];
    const float* b2   = (const float*)d_in[5];
    float*       out  = (float*)d_out;

    cudaFuncSetAttribute(precompute_uv_kernel,
                         cudaFuncAttributeMaxDynamicSharedMemorySize,
                         128 * 128 * sizeof(float));

    // Kernel 1: 12500 warps (8 nodes each) -> 1563 blocks of 256 threads
    // (block 0 also detects the edge_index dtype)
    {
        int warps = (N_NODES + 7) / 8;
        int blocks = (warps * 32 + 255) / 256;
        precompute_uv_kernel<<<blocks, 256, 128 * 128 * sizeof(float)>>>(
            emb, W1, (const int*)eidx);
    }

    // Kernel 2: 8 threads per edge
    {
        long long threads = (long long)N_EDGES * 8;
        int blocks = (int)((threads + 255) / 256);
        edge_score_kernel<<<blocks, 256>>>(eidx, b1, W2, b2, out);
    }
}

// round 10
// speedup vs baseline: 1.7304x; 1.1836x over previous
#include <cuda_runtime.h>
#include <cuda_bf16.h>
#include <cuda_fp16.h>
#include <cstdint>

#define N_NODES 100000
#define EMB_DIM 128
#define HIDDEN  64
#define N_EDGES 1600000
#define EPT     4                         // edges per thread (kernel 2)
#define N_GROUPS (N_EDGES / EPT)          // 400000 8-lane groups

// Scratch: per-node precomputed [u | v] in fp16, 128 halves = 256 B per node
// (25.6 MB; u = cols 0..63 -> one 128B line, v = cols 64..127 -> one line)
__device__ __half g_UVh[(size_t)N_NODES * 128];
// 1 if edge_index is int64 on device, 0 if int32.
__device__ int g_idx_is_64;

// ---------------------------------------------------------------------------
// Kernel 1: UV[n][j] = sum_k emb[n][k] * Wc[k][j]   (fp32 math, fp16 store)
//   Wc[k][j] = W1[k][j]        for j <  64   (u half)
//   Wc[k][j] = W1[128+k][j-64] for j >= 64   (v half)
// One warp computes 8 nodes; lane owns 4 output cols (4*lane .. 4*lane+3).
// Wc (128x128 fp32 = 64 KB) staged in dynamic shared memory per block.
// Block 0 additionally detects the edge_index dtype (int32 vs int64).
// ---------------------------------------------------------------------------
extern __shared__ float sW[];  // 128*128 floats

__global__ __launch_bounds__(256)
void precompute_uv_kernel(const float* __restrict__ emb,
                          const float* __restrict__ W1,
                          const int* __restrict__ eidx32) {
    __shared__ int s_any;
    if (blockIdx.x == 0) {
        if (threadIdx.x == 0) s_any = 0;
        __syncthreads();
        if (threadIdx.x < 128) {
            int w = eidx32[2 * ((int)threadIdx.x * 37 + 1) + 1];
            if (w != 0) atomicOr(&s_any, 1);
        }
        __syncthreads();
        if (threadIdx.x == 0) g_idx_is_64 = (s_any == 0) ? 1 : 0;
    }

    for (int i = threadIdx.x; i < 128 * 64; i += blockDim.x) {
        int k = i >> 6;
        int h = i & 63;
        sW[k * 128 + h]      = W1[k * 64 + h];
        sW[k * 128 + 64 + h] = W1[(128 + k) * 64 + h];
    }
    __syncthreads();

    int warp = (blockIdx.x * blockDim.x + threadIdx.x) >> 5;
    int lane = threadIdx.x & 31;
    int node0 = warp * 8;
    if (node0 >= N_NODES) return;

    float4 acc[8];
    #pragma unroll
    for (int n = 0; n < 8; n++) acc[n] = make_float4(0.f, 0.f, 0.f, 0.f);

    const float* embp = emb + (size_t)node0 * EMB_DIM;

    #pragma unroll 4
    for (int kc = 0; kc < 128; kc += 4) {
        float4 e[8];
        #pragma unroll
        for (int n = 0; n < 8; n++)
            e[n] = *(const float4*)(embp + n * EMB_DIM + kc);

        #pragma unroll
        for (int kk = 0; kk < 4; kk++) {
            float4 w = *(const float4*)(&sW[(kc + kk) * 128 + lane * 4]);
            #pragma unroll
            for (int n = 0; n < 8; n++) {
                float ev = (kk == 0) ? e[n].x : (kk == 1) ? e[n].y
                         : (kk == 2) ? e[n].z : e[n].w;
                acc[n].x = fmaf(ev, w.x, acc[n].x);
                acc[n].y = fmaf(ev, w.y, acc[n].y);
                acc[n].z = fmaf(ev, w.z, acc[n].z);
                acc[n].w = fmaf(ev, w.w, acc[n].w);
            }
        }
    }

    #pragma unroll
    for (int n = 0; n < 8; n++) {
        __half2 h0 = __floats2half2_rn(acc[n].x, acc[n].y);
        __half2 h1 = __floats2half2_rn(acc[n].z, acc[n].w);
        uint2 packed;
        packed.x = *(uint32_t*)&h0;
        packed.y = *(uint32_t*)&h1;
        *(uint2*)(g_UVh + (size_t)(node0 + n) * 128 + lane * 4) = packed;
    }
}

// ---------------------------------------------------------------------------
// Kernel 2: per-edge score, 8 lanes per edge, 4 edges per thread.
// Lane s owns cols 8s..8s+7 (16 B); each gather's 8-lane group = one 128B line.
//   z = relu2(u + v + b1)  in half2;  dot with W2 in fp32.
// Indices: values < 100000 always fit int32; for int64 input the low word of
// eidx64[e] is eidx32[2e] -> pure 32-bit index path either way.
// b1/W2/b2 live in registers (L1-broadcast loads), no smem, no syncthreads.
// ---------------------------------------------------------------------------
__global__ __launch_bounds__(256)
void edge_score_kernel(const int* __restrict__ eidx32,
                       const float* __restrict__ b1,
                       const float* __restrict__ W2,
                       const float* __restrict__ b2,
                       float* __restrict__ out) {
    int gtid = blockIdx.x * blockDim.x + threadIdx.x;
    int group = gtid >> 3;
    if (group >= N_GROUPS) return;
    int s = gtid & 7;

    // index addressing: stride 2 + offset for int64 input, else stride 1
    int is64 = g_idx_is_64;
    int stride = is64 ? 2 : 1;

    // per-lane constants (registers)
    float4 bA = *(const float4*)(b1 + s * 8);
    float4 bB = *(const float4*)(b1 + s * 8 + 4);
    __half2 bh0 = __floats2half2_rn(bA.x, bA.y);
    __half2 bh1 = __floats2half2_rn(bA.z, bA.w);
    __half2 bh2 = __floats2half2_rn(bB.x, bB.y);
    __half2 bh3 = __floats2half2_rn(bB.z, bB.w);
    float4 w0 = *(const float4*)(W2 + s * 8);
    float4 w1 = *(const float4*)(W2 + s * 8 + 4);
    float bias2 = b2[0];
    __half2 zero2 = __floats2half2_rn(0.f, 0.f);

    #pragma unroll
    for (int j = 0; j < EPT; j++) {
        int e = group + j * N_GROUPS;            // < N_EDGES by construction
        int src = eidx32[(size_t)e * stride];
        int tgt = eidx32[((size_t)(N_EDGES + e)) * stride];

        uint4 uraw = *(const uint4*)(g_UVh + (size_t)src * 128 + s * 8);
        uint4 vraw = *(const uint4*)(g_UVh + (size_t)tgt * 128 + 64 + s * 8);
        const __half2* u = (const __half2*)&uraw;
        const __half2* v = (const __half2*)&vraw;

        __half2 z0 = __hmax2(__hadd2(__hadd2(u[0], v[0]), bh0), zero2);
        __half2 z1 = __hmax2(__hadd2(__hadd2(u[1], v[1]), bh1), zero2);
        __half2 z2 = __hmax2(__hadd2(__hadd2(u[2], v[2]), bh2), zero2);
        __half2 z3 = __hmax2(__hadd2(__hadd2(u[3], v[3]), bh3), zero2);

        float2 f0 = __half22float2(z0);
        float2 f1 = __half22float2(z1);
        float2 f2 = __half22float2(z2);
        float2 f3 = __half22float2(z3);

        float p;
        p = f0.x * w0.x;
        p = fmaf(f0.y, w0.y, p);
        p = fmaf(f1.x, w0.z, p);
        p = fmaf(f1.y, w0.w, p);
        p = fmaf(f2.x, w1.x, p);
        p = fmaf(f2.y, w1.y, p);
        p = fmaf(f3.x, w1.z, p);
        p = fmaf(f3.y, w1.w, p);

        p += __shfl_xor_sync(0xFFFFFFFFu, p, 4);
        p += __shfl_xor_sync(0xFFFFFFFFu, p, 2);
        p += __shfl_xor_sync(0xFFFFFFFFu, p, 1);

        if (s == 0) out[e] = p + bias2;
    }
}

// ---------------------------------------------------------------------------
extern "C" void kernel_launch(void* const* d_in, const int* in_sizes, int n_in,
                              void* d_out, int out_size) {
    const float* emb  = (const float*)d_in[0];
    const void*  eidx = d_in[1];
    const float* W1   = (const float*)d_in[2];
    const float* b1   = (const float*)d_in[3];
    const float* W2   = (const float*)d_in[4];
    const float* b2   = (const float*)d_in[5];
    float*       out  = (float*)d_out;

    cudaFuncSetAttribute(precompute_uv_kernel,
                         cudaFuncAttributeMaxDynamicSharedMemorySize,
                         128 * 128 * sizeof(float));

    // Kernel 1: 12500 warps (8 nodes each) -> 1563 blocks of 256 threads
    {
        int warps = (N_NODES + 7) / 8;
        int blocks = (warps * 32 + 255) / 256;
        precompute_uv_kernel<<<blocks, 256, 128 * 128 * sizeof(float)>>>(
            emb, W1, (const int*)eidx);
    }

    // Kernel 2: 8 threads per 4 edges -> 400000 groups * 8 / 256 = 12500 blocks
    {
        int blocks = (N_GROUPS * 8 + 255) / 256;
        edge_score_kernel<<<blocks, 256>>>((const int*)eidx, b1, W2, b2, out);
    }
}

// round 11
// speedup vs baseline: 1.9840x; 1.1466x over previous
#include <cuda_runtime.h>
#include <cuda_bf16.h>
#include <cuda_fp16.h>
#include <cstdint>

#define N_NODES 100000
#define EMB_DIM 128
#define HIDDEN  64
#define N_EDGES 1600000
#define EPT     4                         // edges per thread (kernel 2)
#define N_GROUPS (N_EDGES / EPT)          // 400000 8-lane groups

// Scratch: per-node precomputed [u+b1 | v] in fp16, 128 halves = 256 B/node
// (25.6 MB; u = cols 0..63 -> one 128B line, v = cols 64..127 -> one line)
__device__ __half g_UVh[(size_t)N_NODES * 128];
// 1 if edge_index is int64 on device, 0 if int32.
__device__ int g_idx_is_64;

// ---------------------------------------------------------------------------
// Kernel 1: UV[n][j] = sum_k emb[n][k] * Wc[k][j]  (+ b1[j] for j<64)
//   Wc[k][j] = W1[k][j]        for j <  64   (u half)
//   Wc[k][j] = W1[128+k][j-64] for j >= 64   (v half)
// fp32 math, fp16 store. One warp computes 8 nodes; lane owns 4 output cols.
// Wc (128x128 fp32 = 64 KB) staged in dynamic shared memory per block.
// Block 0 additionally detects the edge_index dtype (int32 vs int64).
// ---------------------------------------------------------------------------
extern __shared__ float sW[];  // 128*128 floats

__global__ __launch_bounds__(256)
void precompute_uv_kernel(const float* __restrict__ emb,
                          const float* __restrict__ W1,
                          const float* __restrict__ b1,
                          const int* __restrict__ eidx32) {
    __shared__ int s_any;
    if (blockIdx.x == 0) {
        if (threadIdx.x == 0) s_any = 0;
        __syncthreads();
        if (threadIdx.x < 128) {
            int w = eidx32[2 * ((int)threadIdx.x * 37 + 1) + 1];
            if (w != 0) atomicOr(&s_any, 1);
        }
        __syncthreads();
        if (threadIdx.x == 0) g_idx_is_64 = (s_any == 0) ? 1 : 0;
    }

    for (int i = threadIdx.x; i < 128 * 64; i += blockDim.x) {
        int k = i >> 6;
        int h = i & 63;
        sW[k * 128 + h]      = W1[k * 64 + h];
        sW[k * 128 + 64 + h] = W1[(128 + k) * 64 + h];
    }
    __syncthreads();

    int warp = (blockIdx.x * blockDim.x + threadIdx.x) >> 5;
    int lane = threadIdx.x & 31;
    int node0 = warp * 8;
    if (node0 >= N_NODES) return;

    // bias for this lane's 4 cols (only u half, cols < 64 <=> lane < 16)
    float4 bb = (lane < 16) ? *(const float4*)(b1 + lane * 4)
                            : make_float4(0.f, 0.f, 0.f, 0.f);

    float4 acc[8];
    #pragma unroll
    for (int n = 0; n < 8; n++) acc[n] = bb;

    const float* embp = emb + (size_t)node0 * EMB_DIM;

    #pragma unroll 4
    for (int kc = 0; kc < 128; kc += 4) {
        float4 e[8];
        #pragma unroll
        for (int n = 0; n < 8; n++)
            e[n] = *(const float4*)(embp + n * EMB_DIM + kc);

        #pragma unroll
        for (int kk = 0; kk < 4; kk++) {
            float4 w = *(const float4*)(&sW[(kc + kk) * 128 + lane * 4]);
            #pragma unroll
            for (int n = 0; n < 8; n++) {
                float ev = (kk == 0) ? e[n].x : (kk == 1) ? e[n].y
                         : (kk == 2) ? e[n].z : e[n].w;
                acc[n].x = fmaf(ev, w.x, acc[n].x);
                acc[n].y = fmaf(ev, w.y, acc[n].y);
                acc[n].z = fmaf(ev, w.z, acc[n].z);
                acc[n].w = fmaf(ev, w.w, acc[n].w);
            }
        }
    }

    #pragma unroll
    for (int n = 0; n < 8; n++) {
        __half2 h0 = __floats2half2_rn(acc[n].x, acc[n].y);
        __half2 h1 = __floats2half2_rn(acc[n].z, acc[n].w);
        uint2 packed;
        packed.x = *(uint32_t*)&h0;
        packed.y = *(uint32_t*)&h1;
        *(uint2*)(g_UVh + (size_t)(node0 + n) * 128 + lane * 4) = packed;
    }
}

// ---------------------------------------------------------------------------
// Kernel 2: per-edge score, 8 lanes per edge, 4 edges per thread.
// Lane s owns cols 8s..8s+7 (16 B); each gather's 8-lane group = one 128B line.
//   z = relu2(u' + v)  in half2  (b1 pre-folded into u');  dot with W2 in fp32.
// Index path is pure 32-bit (int64 low word = eidx32[2e]).
// All loads batched up-front for max memory-level parallelism.
// ---------------------------------------------------------------------------
__global__ __launch_bounds__(256)
void edge_score_kernel(const int* __restrict__ eidx32,
                       const float* __restrict__ W2,
                       const float* __restrict__ b2,
                       float* __restrict__ out) {
    int gtid = blockIdx.x * blockDim.x + threadIdx.x;
    int group = gtid >> 3;
    if (group >= N_GROUPS) return;
    int s = gtid & 7;

    int stride = g_idx_is_64 ? 2 : 1;

    float4 w0 = *(const float4*)(W2 + s * 8);
    float4 w1 = *(const float4*)(W2 + s * 8 + 4);
    float bias2 = b2[0];
    __half2 zero2 = __floats2half2_rn(0.f, 0.f);

    // batch 1: indices
    int src[EPT], tgt[EPT];
    #pragma unroll
    for (int j = 0; j < EPT; j++) {
        int e = group + j * N_GROUPS;
        src[j] = eidx32[(size_t)e * stride];
        tgt[j] = eidx32[((size_t)(N_EDGES + e)) * stride];
    }

    // batch 2: gathers (8 independent 128B-line loads in flight)
    uint4 uraw[EPT], vraw[EPT];
    #pragma unroll
    for (int j = 0; j < EPT; j++) {
        uraw[j] = *(const uint4*)(g_UVh + (size_t)src[j] * 128 + s * 8);
        vraw[j] = *(const uint4*)(g_UVh + (size_t)tgt[j] * 128 + 64 + s * 8);
    }

    // batch 3: math + reduce + store
    #pragma unroll
    for (int j = 0; j < EPT; j++) {
        const __half2* u = (const __half2*)&uraw[j];
        const __half2* v = (const __half2*)&vraw[j];

        __half2 z0 = __hmax2(__hadd2(u[0], v[0]), zero2);
        __half2 z1 = __hmax2(__hadd2(u[1], v[1]), zero2);
        __half2 z2 = __hmax2(__hadd2(u[2], v[2]), zero2);
        __half2 z3 = __hmax2(__hadd2(u[3], v[3]), zero2);

        float2 f0 = __half22float2(z0);
        float2 f1 = __half22float2(z1);
        float2 f2 = __half22float2(z2);
        float2 f3 = __half22float2(z3);

        float p;
        p = f0.x * w0.x;
        p = fmaf(f0.y, w0.y, p);
        p = fmaf(f1.x, w0.z, p);
        p = fmaf(f1.y, w0.w, p);
        p = fmaf(f2.x, w1.x, p);
        p = fmaf(f2.y, w1.y, p);
        p = fmaf(f3.x, w1.z, p);
        p = fmaf(f3.y, w1.w, p);

        p += __shfl_xor_sync(0xFFFFFFFFu, p, 4);
        p += __shfl_xor_sync(0xFFFFFFFFu, p, 2);
        p += __shfl_xor_sync(0xFFFFFFFFu, p, 1);

        if (s == 0) out[group + j * N_GROUPS] = p + bias2;
    }
}

// ---------------------------------------------------------------------------
extern "C" void kernel_launch(void* const* d_in, const int* in_sizes, int n_in,
                              void* d_out, int out_size) {
    const float* emb  = (const float*)d_in[0];
    const void*  eidx = d_in[1];
    const float* W1   = (const float*)d_in[2];
    const float* b1   = (const float*)d_in[3];
    const float* W2   = (const float*)d_in[4];
    const float* b2   = (const float*)d_in[5];
    float*       out  = (float*)d_out;

    cudaFuncSetAttribute(precompute_uv_kernel,
                         cudaFuncAttributeMaxDynamicSharedMemorySize,
                         128 * 128 * sizeof(float));

    // Kernel 1: 12500 warps (8 nodes each) -> 1563 blocks of 256 threads
    {
        int warps = (N_NODES + 7) / 8;
        int blocks = (warps * 32 + 255) / 256;
        precompute_uv_kernel<<<blocks, 256, 128 * 128 * sizeof(float)>>>(
            emb, W1, b1, (const int*)eidx);
    }

    // Kernel 2: 8 threads per 4 edges -> 12500 blocks of 256 threads
    {
        int blocks = (N_GROUPS * 8 + 255) / 256;
        edge_score_kernel<<<blocks, 256>>>((const int*)eidx, W2, b2, out);
    }
}

// round 12
// speedup vs baseline: 2.1645x; 1.0910x over previous
#include <cuda_runtime.h>
#include <cuda_bf16.h>
#include <cuda_fp16.h>
#include <cstdint>

#define N_NODES 100000
#define EMB_DIM 128
#define HIDDEN  64
#define N_EDGES 1600000
#define EPT     4                         // edges per thread (kernel 2)
#define N_GROUPS (N_EDGES / EPT)          // 400000 8-lane groups

// Scratch: per-node precomputed [u+b1 | v] in fp16, 128 halves = 256 B/node
// (25.6 MB; u = cols 0..63 -> one 128B line, v = cols 64..127 -> one line)
__device__ __half g_UVh[(size_t)N_NODES * 128];
// 1 if edge_index is int64 on device, 0 if int32.
__device__ int g_idx_is_64;

// ---------------------------------------------------------------------------
// Kernel 1: UV[n][j] = sum_k emb[n][k] * Wc[k][j]  (+ b1[j] for j<64)
//   Wc[k][j] = W1[k][j]        for j <  64   (u half)
//   Wc[k][j] = W1[128+k][j-64] for j >= 64   (v half)
// fp32 math, fp16 store. One warp computes 8 nodes; lane owns 4 output cols.
// NO smem staging: W1 (64 KB) is L1-resident; each lane reads its 16B weight
// slice per k directly (lanes 0-15 -> W1 row k, lanes 16-31 -> row 128+k).
// Block 0 additionally detects the edge_index dtype (int32 vs int64).
// ---------------------------------------------------------------------------
__global__ __launch_bounds__(256)
void precompute_uv_kernel(const float* __restrict__ emb,
                          const float* __restrict__ W1,
                          const float* __restrict__ b1,
                          const int* __restrict__ eidx32) {
    __shared__ int s_any;
    if (blockIdx.x == 0) {
        if (threadIdx.x == 0) s_any = 0;
        __syncthreads();
        if (threadIdx.x < 128) {
            int w = eidx32[2 * ((int)threadIdx.x * 37 + 1) + 1];
            if (w != 0) atomicOr(&s_any, 1);
        }
        __syncthreads();
        if (threadIdx.x == 0) g_idx_is_64 = (s_any == 0) ? 1 : 0;
    }

    int warp = (blockIdx.x * blockDim.x + threadIdx.x) >> 5;
    int lane = threadIdx.x & 31;
    int node0 = warp * 8;
    if (node0 >= N_NODES) return;

    // per-lane weight base: lane<16 -> u half (W1 rows 0..127, col lane*4)
    //                       lane>=16 -> v half (W1 rows 128..255, col (lane-16)*4)
    const float* wbase = W1 + ((lane < 16) ? (lane * 4)
                                           : (128 * 64 + (lane - 16) * 4));

    // bias fold (u half only)
    float4 bb = (lane < 16) ? *(const float4*)(b1 + lane * 4)
                            : make_float4(0.f, 0.f, 0.f, 0.f);

    float4 acc[8];
    #pragma unroll
    for (int n = 0; n < 8; n++) acc[n] = bb;

    const float* embp = emb + (size_t)node0 * EMB_DIM;

    #pragma unroll 4
    for (int kc = 0; kc < 128; kc += 4) {
        float4 e[8];
        #pragma unroll
        for (int n = 0; n < 8; n++)
            e[n] = *(const float4*)(embp + n * EMB_DIM + kc);

        #pragma unroll
        for (int kk = 0; kk < 4; kk++) {
            float4 w = *(const float4*)(wbase + (kc + kk) * 64);
            #pragma unroll
            for (int n = 0; n < 8; n++) {
                float ev = (kk == 0) ? e[n].x : (kk == 1) ? e[n].y
                         : (kk == 2) ? e[n].z : e[n].w;
                acc[n].x = fmaf(ev, w.x, acc[n].x);
                acc[n].y = fmaf(ev, w.y, acc[n].y);
                acc[n].z = fmaf(ev, w.z, acc[n].z);
                acc[n].w = fmaf(ev, w.w, acc[n].w);
            }
        }
    }

    #pragma unroll
    for (int n = 0; n < 8; n++) {
        __half2 h0 = __floats2half2_rn(acc[n].x, acc[n].y);
        __half2 h1 = __floats2half2_rn(acc[n].z, acc[n].w);
        uint2 packed;
        packed.x = *(uint32_t*)&h0;
        packed.y = *(uint32_t*)&h1;
        *(uint2*)(g_UVh + (size_t)(node0 + n) * 128 + lane * 4) = packed;
    }
}

// ---------------------------------------------------------------------------
// Kernel 2: per-edge score, 8 lanes per edge, 4 edges per thread.
// Lane s owns cols 8s..8s+7 (16 B); each gather's 8-lane group = one 128B line.
//   z = relu2(u' + v)  in half2  (b1 pre-folded into u');  dot with W2 in fp32.
// Index path is pure 32-bit (int64 low word = eidx32[2e]).
// All loads batched up-front for max memory-level parallelism.
// ---------------------------------------------------------------------------
__global__ __launch_bounds__(256)
void edge_score_kernel(const int* __restrict__ eidx32,
                       const float* __restrict__ W2,
                       const float* __restrict__ b2,
                       float* __restrict__ out) {
    int gtid = blockIdx.x * blockDim.x + threadIdx.x;
    int group = gtid >> 3;
    if (group >= N_GROUPS) return;
    int s = gtid & 7;

    int stride = g_idx_is_64 ? 2 : 1;

    float4 w0 = *(const float4*)(W2 + s * 8);
    float4 w1 = *(const float4*)(W2 + s * 8 + 4);
    float bias2 = b2[0];
    __half2 zero2 = __floats2half2_rn(0.f, 0.f);

    // batch 1: indices
    int src[EPT], tgt[EPT];
    #pragma unroll
    for (int j = 0; j < EPT; j++) {
        int e = group + j * N_GROUPS;
        src[j] = eidx32[(size_t)e * stride];
        tgt[j] = eidx32[((size_t)(N_EDGES + e)) * stride];
    }

    // batch 2: gathers (8 independent 128B-line loads in flight)
    uint4 uraw[EPT], vraw[EPT];
    #pragma unroll
    for (int j = 0; j < EPT; j++) {
        uraw[j] = *(const uint4*)(g_UVh + (size_t)src[j] * 128 + s * 8);
        vraw[j] = *(const uint4*)(g_UVh + (size_t)tgt[j] * 128 + 64 + s * 8);
    }

    // batch 3: math + reduce + store
    #pragma unroll
    for (int j = 0; j < EPT; j++) {
        const __half2* u = (const __half2*)&uraw[j];
        const __half2* v = (const __half2*)&vraw[j];

        __half2 z0 = __hmax2(__hadd2(u[0], v[0]), zero2);
        __half2 z1 = __hmax2(__hadd2(u[1], v[1]), zero2);
        __half2 z2 = __hmax2(__hadd2(u[2], v[2]), zero2);
        __half2 z3 = __hmax2(__hadd2(u[3], v[3]), zero2);

        float2 f0 = __half22float2(z0);
        float2 f1 = __half22float2(z1);
        float2 f2 = __half22float2(z2);
        float2 f3 = __half22float2(z3);

        float p;
        p = f0.x * w0.x;
        p = fmaf(f0.y, w0.y, p);
        p = fmaf(f1.x, w0.z, p);
        p = fmaf(f1.y, w0.w, p);
        p = fmaf(f2.x, w1.x, p);
        p = fmaf(f2.y, w1.y, p);
        p = fmaf(f3.x, w1.z, p);
        p = fmaf(f3.y, w1.w, p);

        p += __shfl_xor_sync(0xFFFFFFFFu, p, 4);
        p += __shfl_xor_sync(0xFFFFFFFFu, p, 2);
        p += __shfl_xor_sync(0xFFFFFFFFu, p, 1);

        if (s == 0) out[group + j * N_GROUPS] = p + bias2;
    }
}

// ---------------------------------------------------------------------------
extern "C" void kernel_launch(void* const* d_in, const int* in_sizes, int n_in,
                              void* d_out, int out_size) {
    const float* emb  = (const float*)d_in[0];
    const void*  eidx = d_in[1];
    const float* W1   = (const float*)d_in[2];
    const float* b1   = (const float*)d_in[3];
    const float* W2   = (const float*)d_in[4];
    const float* b2   = (const float*)d_in[5];
    float*       out  = (float*)d_out;

    // Kernel 1: 12500 warps (8 nodes each) -> 1563 blocks of 256 threads
    {
        int warps = (N_NODES + 7) / 8;
        int blocks = (warps * 32 + 255) / 256;
        precompute_uv_kernel<<<blocks, 256>>>(emb, W1, b1, (const int*)eidx);
    }

    // Kernel 2: 8 threads per 4 edges -> 12500 blocks of 256 threads
    {
        int blocks = (N_GROUPS * 8 + 255) / 256;
        edge_score_kernel<<<blocks, 256>>>((const int*)eidx, W2, b2, out);
    }
}

// round 13
// speedup vs baseline: 2.6615x; 1.2296x over previous
#include <cuda_runtime.h>
#include <cuda_bf16.h>
#include <cuda_fp16.h>
#include <cstdint>

#define N_NODES 100000
#define EMB_DIM 128
#define HIDDEN  64
#define N_EDGES 1600000
#define EPT     4
#define N_GROUPS (N_EDGES / EPT)          // 400000 8-lane groups
#define TILE_M  128
#define N_TILES ((N_NODES + TILE_M - 1) / TILE_M)   // 782

// Scratch: per-node precomputed [u+b1 | v] in fp16, 128 halves = 256 B/node
__device__ __half g_UVh[(size_t)N_NODES * 128];
// 1 if edge_index is int64 on device, 0 if int32.
__device__ int g_idx_is_64;

// ---- kernel-1 smem: B tiles only (hi, lo), 272B row stride (conflict-free)
#define ROW_BYTES 272
#define BTILE (128 * ROW_BYTES)            // 34816
#define SM_B_HI 0
#define SM_B_LO BTILE
#define SMEM_K1 (2 * BTILE)                // 69632 B -> 2 CTAs/SM

__device__ __forceinline__ void mma_bf16(float* d, uint32_t a0, uint32_t a1,
                                         uint32_t a2, uint32_t a3,
                                         uint32_t b0, uint32_t b1) {
    asm volatile(
        "mma.sync.aligned.m16n8k16.row.col.f32.bf16.bf16.f32 "
        "{%0,%1,%2,%3}, {%4,%5,%6,%7}, {%8,%9}, {%0,%1,%2,%3};"
        : "+f"(d[0]), "+f"(d[1]), "+f"(d[2]), "+f"(d[3])
        : "r"(a0), "r"(a1), "r"(a2), "r"(a3), "r"(b0), "r"(b1));
}

__device__ __forceinline__ uint32_t bf2_hi(float x0, float x1) {
    __nv_bfloat162 h;
    h.x = __float2bfloat16(x0); h.y = __float2bfloat16(x1);
    return *(uint32_t*)&h;
}
__device__ __forceinline__ uint32_t bf2_lo(float x0, float x1, uint32_t hp) {
    __nv_bfloat162 h = *(__nv_bfloat162*)&hp;
    __nv_bfloat162 l;
    l.x = __float2bfloat16(x0 - __bfloat162float(h.x));
    l.y = __float2bfloat16(x1 - __bfloat162float(h.y));
    return *(uint32_t*)&l;
}

// ---------------------------------------------------------------------------
// Kernel 1 (warp-MMA v3): UV[m][n] = sum_k emb[m][k]*Wc[k][n] (+b1[n], n<64)
//   Wc[k][n] = W1[k][n] (n<64) | W1[128+k][n-64] (n>=64)
// Split-bf16 3-term: Ahi*Bhi + Ahi*Blo + Alo*Bhi, fp32 accum, fp16 store.
// 8 warps/CTA; warp w -> rows [16w,16w+16). A streamed gmem->regs per k-step
// (no smem). B (transposed Wt[n][k], hi+lo) staged once in smem, coalesced.
// Fragment maps identical to the R7-verified ones. Block 0 detects eidx dtype.
// ---------------------------------------------------------------------------
__global__ __launch_bounds__(256)
void precompute_uv_mma(const float* __restrict__ emb,
                       const float* __restrict__ W1,
                       const float* __restrict__ b1,
                       const int* __restrict__ eidx32) {
    extern __shared__ char smem[];
    int tid = threadIdx.x;

    __shared__ int s_any;
    if (blockIdx.x == 0) {
        if (tid == 0) s_any = 0;
        __syncthreads();
        if (tid < 128) {
            int w = eidx32[2 * (tid * 37 + 1) + 1];
            if (w != 0) atomicOr(&s_any, 1);
        }
        __syncthreads();
        if (tid == 0) g_idx_is_64 = (s_any == 0) ? 1 : 0;
    }

    // --- stage B hi/lo: coalesced float2 LDG of W1 [256,64], transpose on STS
    //   W1 row r, col c -> Wt[n=c+64*(r>=128)][k=r%128]
    for (int i = tid; i < 128 * 64; i += 256) {
        float2 x = *(const float2*)(W1 + 2 * (size_t)i);
        int r = (2 * i) >> 6;
        int c = (2 * i) & 63;
        int k = r & 127;
        int n = c + ((r >> 7) << 6);
        uint32_t hp = bf2_hi(x.x, x.y);
        uint32_t lp = bf2_lo(x.x, x.y, hp);
        __nv_bfloat162 h = *(__nv_bfloat162*)&hp;
        __nv_bfloat162 l = *(__nv_bfloat162*)&lp;
        char* bh = smem + SM_B_HI + n * ROW_BYTES + k * 2;
        char* bl = smem + SM_B_LO + n * ROW_BYTES + k * 2;
        *(__nv_bfloat16*)(bh)             = h.x;
        *(__nv_bfloat16*)(bh + ROW_BYTES) = h.y;   // n+1, same k
        *(__nv_bfloat16*)(bl)             = l.x;
        *(__nv_bfloat16*)(bl + ROW_BYTES) = l.y;
    }
    __syncthreads();

    int wid = tid >> 5, lane = tid & 31;
    int g = lane >> 2, t = lane & 3;
    int base = blockIdx.x * TILE_M;
    int m0 = wid * 16;

    // clamped row indices for A loads (stores are guarded; values don't matter)
    int rowA = base + m0 + g;       if (rowA >= N_NODES) rowA = N_NODES - 1;
    int rowB = base + m0 + 8 + g;   if (rowB >= N_NODES) rowB = N_NODES - 1;
    const float* embA = emb + (size_t)rowA * EMB_DIM + 2 * t;
    const float* embB = emb + (size_t)rowB * EMB_DIM + 2 * t;

    // accumulators: 16 n-tiles x 4; init with b1 (cols < 64 only)
    float acc[16][4];
    #pragma unroll
    for (int nt = 0; nt < 16; nt++) {
        int col = 8 * nt + 2 * t;
        if (col < 64) {
            float2 b = *(const float2*)(b1 + col);
            acc[nt][0] = b.x; acc[nt][1] = b.y;
            acc[nt][2] = b.x; acc[nt][3] = b.y;
        } else {
            acc[nt][0] = acc[nt][1] = acc[nt][2] = acc[nt][3] = 0.f;
        }
    }

    const char* BH = smem + SM_B_HI;
    const char* BL = smem + SM_B_LO;
    // b-row byte offset for this lane within an n-tile: row (8nt+g)
    int brow = g * ROW_BYTES;

    #pragma unroll
    for (int ks = 0; ks < 8; ks++) {
        int k0 = ks * 16;
        // A fragments from gmem (verified map):
        //  a0={A[g][k0+2t..+1]}  a1={A[8+g][..]}  a2={A[g][k0+2t+8..]}  a3={A[8+g][+8]}
        float2 xa0 = *(const float2*)(embA + k0);
        float2 xa1 = *(const float2*)(embB + k0);
        float2 xa2 = *(const float2*)(embA + k0 + 8);
        float2 xa3 = *(const float2*)(embB + k0 + 8);
        uint32_t ah0 = bf2_hi(xa0.x, xa0.y), al0 = bf2_lo(xa0.x, xa0.y, ah0);
        uint32_t ah1 = bf2_hi(xa1.x, xa1.y), al1 = bf2_lo(xa1.x, xa1.y, ah1);
        uint32_t ah2 = bf2_hi(xa2.x, xa2.y), al2 = bf2_lo(xa2.x, xa2.y, ah2);
        uint32_t ah3 = bf2_hi(xa3.x, xa3.y), al3 = bf2_lo(xa3.x, xa3.y, ah3);

        int kb0 = (k0 + 2 * t) * 2;       // byte offset of b0 within row
        int kb1 = (k0 + 2 * t + 8) * 2;   // byte offset of b1
        #pragma unroll
        for (int nt = 0; nt < 16; nt++) {
            int roff = nt * 8 * ROW_BYTES + brow;
            uint32_t bh0 = *(const uint32_t*)(BH + roff + kb0);
            uint32_t bh1 = *(const uint32_t*)(BH + roff + kb1);
            uint32_t bl0 = *(const uint32_t*)(BL + roff + kb0);
            uint32_t bl1 = *(const uint32_t*)(BL + roff + kb1);
            mma_bf16(acc[nt], ah0, ah1, ah2, ah3, bh0, bh1);
            mma_bf16(acc[nt], ah0, ah1, ah2, ah3, bl0, bl1);
            mma_bf16(acc[nt], al0, al1, al2, al3, bh0, bh1);
        }
    }

    // --- epilogue: fp16 store. lane owns D[g][2t..+1], D[8+g][2t..+1] per nt
    int node0 = base + m0 + g;
    int node1 = base + m0 + 8 + g;
    #pragma unroll
    for (int nt = 0; nt < 16; nt++) {
        int col = 8 * nt + 2 * t;
        if (node0 < N_NODES) {
            __half2 h = __floats2half2_rn(acc[nt][0], acc[nt][1]);
            *(__half2*)(g_UVh + (size_t)node0 * 128 + col) = h;
        }
        if (node1 < N_NODES) {
            __half2 h = __floats2half2_rn(acc[nt][2], acc[nt][3]);
            *(__half2*)(g_UVh + (size_t)node1 * 128 + col) = h;
        }
    }
}

// ---------------------------------------------------------------------------
// Kernel 2: per-edge score (unchanged R11/R12 winner).
// 8 lanes per edge, 4 edges per thread; each gather = one 128B line.
// ---------------------------------------------------------------------------
__global__ __launch_bounds__(256)
void edge_score_kernel(const int* __restrict__ eidx32,
                       const float* __restrict__ W2,
                       const float* __restrict__ b2,
                       float* __restrict__ out) {
    int gtid = blockIdx.x * blockDim.x + threadIdx.x;
    int group = gtid >> 3;
    if (group >= N_GROUPS) return;
    int s = gtid & 7;

    int stride = g_idx_is_64 ? 2 : 1;

    float4 w0 = *(const float4*)(W2 + s * 8);
    float4 w1 = *(const float4*)(W2 + s * 8 + 4);
    float bias2 = b2[0];
    __half2 zero2 = __floats2half2_rn(0.f, 0.f);

    int src[EPT], tgt[EPT];
    #pragma unroll
    for (int j = 0; j < EPT; j++) {
        int e = group + j * N_GROUPS;
        src[j] = eidx32[(size_t)e * stride];
        tgt[j] = eidx32[((size_t)(N_EDGES + e)) * stride];
    }

    uint4 uraw[EPT], vraw[EPT];
    #pragma unroll
    for (int j = 0; j < EPT; j++) {
        uraw[j] = *(const uint4*)(g_UVh + (size_t)src[j] * 128 + s * 8);
        vraw[j] = *(const uint4*)(g_UVh + (size_t)tgt[j] * 128 + 64 + s * 8);
    }

    #pragma unroll
    for (int j = 0; j < EPT; j++) {
        const __half2* u = (const __half2*)&uraw[j];
        const __half2* v = (const __half2*)&vraw[j];

        __half2 z0 = __hmax2(__hadd2(u[0], v[0]), zero2);
        __half2 z1 = __hmax2(__hadd2(u[1], v[1]), zero2);
        __half2 z2 = __hmax2(__hadd2(u[2], v[2]), zero2);
        __half2 z3 = __hmax2(__hadd2(u[3], v[3]), zero2);

        float2 f0 = __half22float2(z0);
        float2 f1 = __half22float2(z1);
        float2 f2 = __half22float2(z2);
        float2 f3 = __half22float2(z3);

        float p;
        p = f0.x * w0.x;
        p = fmaf(f0.y, w0.y, p);
        p = fmaf(f1.x, w0.z, p);
        p = fmaf(f1.y, w0.w, p);
        p = fmaf(f2.x, w1.x, p);
        p = fmaf(f2.y, w1.y, p);
        p = fmaf(f3.x, w1.z, p);
        p = fmaf(f3.y, w1.w, p);

        p += __shfl_xor_sync(0xFFFFFFFFu, p, 4);
        p += __shfl_xor_sync(0xFFFFFFFFu, p, 2);
        p += __shfl_xor_sync(0xFFFFFFFFu, p, 1);

        if (s == 0) out[group + j * N_GROUPS] = p + bias2;
    }
}

// ---------------------------------------------------------------------------
extern "C" void kernel_launch(void* const* d_in, const int* in_sizes, int n_in,
                              void* d_out, int out_size) {
    const float* emb  = (const float*)d_in[0];
    const void*  eidx = d_in[1];
    const float* W1   = (const float*)d_in[2];
    const float* b1   = (const float*)d_in[3];
    const float* W2   = (const float*)d_in[4];
    const float* b2   = (const float*)d_in[5];
    float*       out  = (float*)d_out;

    cudaFuncSetAttribute(precompute_uv_mma,
                         cudaFuncAttributeMaxDynamicSharedMemorySize, SMEM_K1);

    // Kernel 1: 782 CTAs x 256 threads, 68KB smem -> 2 CTAs/SM
    precompute_uv_mma<<<N_TILES, 256, SMEM_K1>>>(emb, W1, b1, (const int*)eidx);

    // Kernel 2: 8 threads per 4 edges -> 12500 blocks
    {
        int blocks = (N_GROUPS * 8 + 255) / 256;
        edge_score_kernel<<<blocks, 256>>>((const int*)eidx, W2, b2, out);
    }
}

// round 14
// speedup vs baseline: 3.3725x; 1.2671x over previous
#include <cuda_runtime.h>
#include <cuda_bf16.h>
#include <cuda_fp16.h>
#include <cstdint>

#define N_NODES 100000
#define EMB_DIM 128
#define HIDDEN  64
#define N_EDGES 1600000
#define EPT     4
#define N_GROUPS (N_EDGES / EPT)          // 400000 8-lane groups
#define TILE_M  128
#define N_TILES ((N_NODES + TILE_M - 1) / TILE_M)   // 782

// Scratch: per-node precomputed [u+b1 | v] in fp16, 128 halves = 256 B/node
__device__ __half g_UVh[(size_t)N_NODES * 128];
// 1 if edge_index is int64 on device, 0 if int32.
__device__ int g_idx_is_64;

// ---- kernel-1 smem: B tile (fp16 hi only), 272B row stride (conflict-free)
#define ROW_BYTES 272
#define SMEM_K1 (128 * ROW_BYTES)          // 34816 B

__device__ __forceinline__ void mma_f16(float* d, uint32_t a0, uint32_t a1,
                                        uint32_t a2, uint32_t a3,
                                        uint32_t b0, uint32_t b1) {
    asm volatile(
        "mma.sync.aligned.m16n8k16.row.col.f32.f16.f16.f32 "
        "{%0,%1,%2,%3}, {%4,%5,%6,%7}, {%8,%9}, {%0,%1,%2,%3};"
        : "+f"(d[0]), "+f"(d[1]), "+f"(d[2]), "+f"(d[3])
        : "r"(a0), "r"(a1), "r"(a2), "r"(a3), "r"(b0), "r"(b1));
}

__device__ __forceinline__ uint32_t h2_hi(float x0, float x1) {
    __half2 h = __floats2half2_rn(x0, x1);
    return *(uint32_t*)&h;
}
__device__ __forceinline__ uint32_t h2_lo(float x0, float x1, uint32_t hp) {
    __half2 h = *(__half2*)&hp;
    __half2 l = __floats2half2_rn(x0 - __half2float(h.x),
                                  x1 - __half2float(h.y));
    return *(uint32_t*)&l;
}

// ---------------------------------------------------------------------------
// Kernel 1 (warp-MMA v4): UV[m][n] = sum_k emb[m][k]*Wc[k][n] (+b1[n], n<64)
//   Wc[k][n] = W1[k][n] (n<64) | W1[128+k][n-64] (n>=64)
// fp16 2-pass split: D = Ahi*Bhi + Alo*Bhi  (A = Ahi+Alo fp16, B ~ Bhi fp16);
// dropped A*Blo term ~2^-12 rel. fp32 accum, fp16 store.
// 8 warps/CTA; warp w -> rows [16w,16w+16). A streamed gmem->regs per k-step.
// B (transposed Wt[n][k], fp16) staged once in smem, coalesced LDG.
// Fragment maps identical to the R7-verified ones. Block 0 detects eidx dtype.
// ---------------------------------------------------------------------------
__global__ __launch_bounds__(256, 2)
void precompute_uv_mma(const float* __restrict__ emb,
                       const float* __restrict__ W1,
                       const float* __restrict__ b1,
                       const int* __restrict__ eidx32) {
    extern __shared__ char smem[];
    int tid = threadIdx.x;

    __shared__ int s_any;
    if (blockIdx.x == 0) {
        if (tid == 0) s_any = 0;
        __syncthreads();
        if (tid < 128) {
            int w = eidx32[2 * (tid * 37 + 1) + 1];
            if (w != 0) atomicOr(&s_any, 1);
        }
        __syncthreads();
        if (tid == 0) g_idx_is_64 = (s_any == 0) ? 1 : 0;
    }

    // --- stage B (fp16): coalesced float2 LDG of W1 [256,64], transposed STS
    //   W1 row r, col c -> Wt[n=c+64*(r>=128)][k=r%128]
    for (int i = tid; i < 128 * 64; i += 256) {
        float2 x = *(const float2*)(W1 + 2 * (size_t)i);
        int r = (2 * i) >> 6;
        int c = (2 * i) & 63;
        int k = r & 127;
        int n = c + ((r >> 7) << 6);
        __half h0 = __float2half_rn(x.x);
        __half h1 = __float2half_rn(x.y);
        char* bh = smem + n * ROW_BYTES + k * 2;
        *(__half*)(bh)             = h0;
        *(__half*)(bh + ROW_BYTES) = h1;   // n+1, same k
    }
    __syncthreads();

    int wid = tid >> 5, lane = tid & 31;
    int g = lane >> 2, t = lane & 3;
    int base = blockIdx.x * TILE_M;
    int m0 = wid * 16;

    // clamped row indices for A loads (stores are guarded)
    int rowA = base + m0 + g;       if (rowA >= N_NODES) rowA = N_NODES - 1;
    int rowB = base + m0 + 8 + g;   if (rowB >= N_NODES) rowB = N_NODES - 1;
    const float* embA = emb + (size_t)rowA * EMB_DIM + 2 * t;
    const float* embB = emb + (size_t)rowB * EMB_DIM + 2 * t;

    // accumulators: 16 n-tiles x 4; init with b1 (cols < 64 only)
    float acc[16][4];
    #pragma unroll
    for (int nt = 0; nt < 16; nt++) {
        int col = 8 * nt + 2 * t;
        if (col < 64) {
            float2 b = *(const float2*)(b1 + col);
            acc[nt][0] = b.x; acc[nt][1] = b.y;
            acc[nt][2] = b.x; acc[nt][3] = b.y;
        } else {
            acc[nt][0] = acc[nt][1] = acc[nt][2] = acc[nt][3] = 0.f;
        }
    }

    const char* BH = smem;
    int brow = g * ROW_BYTES;

    #pragma unroll
    for (int ks = 0; ks < 8; ks++) {
        int k0 = ks * 16;
        // A fragments (verified map):
        //  a0={A[g][k0+2t..+1]} a1={A[8+g][..]} a2={A[g][k0+2t+8..]} a3={A[8+g][+8]}
        float2 xa0 = *(const float2*)(embA + k0);
        float2 xa1 = *(const float2*)(embB + k0);
        float2 xa2 = *(const float2*)(embA + k0 + 8);
        float2 xa3 = *(const float2*)(embB + k0 + 8);
        uint32_t ah0 = h2_hi(xa0.x, xa0.y), al0 = h2_lo(xa0.x, xa0.y, ah0);
        uint32_t ah1 = h2_hi(xa1.x, xa1.y), al1 = h2_lo(xa1.x, xa1.y, ah1);
        uint32_t ah2 = h2_hi(xa2.x, xa2.y), al2 = h2_lo(xa2.x, xa2.y, ah2);
        uint32_t ah3 = h2_hi(xa3.x, xa3.y), al3 = h2_lo(xa3.x, xa3.y, ah3);

        int kb0 = (k0 + 2 * t) * 2;
        int kb1 = (k0 + 2 * t + 8) * 2;
        #pragma unroll
        for (int nt = 0; nt < 16; nt++) {
            int roff = nt * 8 * ROW_BYTES + brow;
            uint32_t bh0 = *(const uint32_t*)(BH + roff + kb0);
            uint32_t bh1 = *(const uint32_t*)(BH + roff + kb1);
            mma_f16(acc[nt], ah0, ah1, ah2, ah3, bh0, bh1);
            mma_f16(acc[nt], al0, al1, al2, al3, bh0, bh1);
        }
    }

    // --- epilogue: fp16 store. lane owns D[g][2t..+1], D[8+g][2t..+1] per nt
    int node0 = base + m0 + g;
    int node1 = base + m0 + 8 + g;
    #pragma unroll
    for (int nt = 0; nt < 16; nt++) {
        int col = 8 * nt + 2 * t;
        if (node0 < N_NODES) {
            __half2 h = __floats2half2_rn(acc[nt][0], acc[nt][1]);
            *(__half2*)(g_UVh + (size_t)node0 * 128 + col) = h;
        }
        if (node1 < N_NODES) {
            __half2 h = __floats2half2_rn(acc[nt][2], acc[nt][3]);
            *(__half2*)(g_UVh + (size_t)node1 * 128 + col) = h;
        }
    }
}

// ---------------------------------------------------------------------------
// Kernel 2: per-edge score (unchanged R11/R12 winner).
// 8 lanes per edge, 4 edges per thread; each gather = one 128B line.
// ---------------------------------------------------------------------------
__global__ __launch_bounds__(256)
void edge_score_kernel(const int* __restrict__ eidx32,
                       const float* __restrict__ W2,
                       const float* __restrict__ b2,
                       float* __restrict__ out) {
    int gtid = blockIdx.x * blockDim.x + threadIdx.x;
    int group = gtid >> 3;
    if (group >= N_GROUPS) return;
    int s = gtid & 7;

    int stride = g_idx_is_64 ? 2 : 1;

    float4 w0 = *(const float4*)(W2 + s * 8);
    float4 w1 = *(const float4*)(W2 + s * 8 + 4);
    float bias2 = b2[0];
    __half2 zero2 = __floats2half2_rn(0.f, 0.f);

    int src[EPT], tgt[EPT];
    #pragma unroll
    for (int j = 0; j < EPT; j++) {
        int e = group + j * N_GROUPS;
        src[j] = eidx32[(size_t)e * stride];
        tgt[j] = eidx32[((size_t)(N_EDGES + e)) * stride];
    }

    uint4 uraw[EPT], vraw[EPT];
    #pragma unroll
    for (int j = 0; j < EPT; j++) {
        uraw[j] = *(const uint4*)(g_UVh + (size_t)src[j] * 128 + s * 8);
        vraw[j] = *(const uint4*)(g_UVh + (size_t)tgt[j] * 128 + 64 + s * 8);
    }

    #pragma unroll
    for (int j = 0; j < EPT; j++) {
        const __half2* u = (const __half2*)&uraw[j];
        const __half2* v = (const __half2*)&vraw[j];

        __half2 z0 = __hmax2(__hadd2(u[0], v[0]), zero2);
        __half2 z1 = __hmax2(__hadd2(u[1], v[1]), zero2);
        __half2 z2 = __hmax2(__hadd2(u[2], v[2]), zero2);
        __half2 z3 = __hmax2(__hadd2(u[3], v[3]), zero2);

        float2 f0 = __half22float2(z0);
        float2 f1 = __half22float2(z1);
        float2 f2 = __half22float2(z2);
        float2 f3 = __half22float2(z3);

        float p;
        p = f0.x * w0.x;
        p = fmaf(f0.y, w0.y, p);
        p = fmaf(f1.x, w0.z, p);
        p = fmaf(f1.y, w0.w, p);
        p = fmaf(f2.x, w1.x, p);
        p = fmaf(f2.y, w1.y, p);
        p = fmaf(f3.x, w1.z, p);
        p = fmaf(f3.y, w1.w, p);

        p += __shfl_xor_sync(0xFFFFFFFFu, p, 4);
        p += __shfl_xor_sync(0xFFFFFFFFu, p, 2);
        p += __shfl_xor_sync(0xFFFFFFFFu, p, 1);

        if (s == 0) out[group + j * N_GROUPS] = p + bias2;
    }
}

// ---------------------------------------------------------------------------
extern "C" void kernel_launch(void* const* d_in, const int* in_sizes, int n_in,
                              void* d_out, int out_size) {
    const float* emb  = (const float*)d_in[0];
    const void*  eidx = d_in[1];
    const float* W1   = (const float*)d_in[2];
    const float* b1   = (const float*)d_in[3];
    const float* W2   = (const float*)d_in[4];
    const float* b2   = (const float*)d_in[5];
    float*       out  = (float*)d_out;

    // Kernel 1: 782 CTAs x 256 threads, 34.8KB smem
    precompute_uv_mma<<<N_TILES, 256, SMEM_K1>>>(emb, W1, b1, (const int*)eidx);

    // Kernel 2: 8 threads per 4 edges -> 12500 blocks
    {
        int blocks = (N_GROUPS * 8 + 255) / 256;
        edge_score_kernel<<<blocks, 256>>>((const int*)eidx, W2, b2, out);
    }
}

// round 15
// speedup vs baseline: 3.4519x; 1.0235x over previous
#include <cuda_runtime.h>
#include <cuda_bf16.h>
#include <cuda_fp16.h>
#include <cstdint>

#define N_NODES 100000
#define EMB_DIM 128
#define HIDDEN  64
#define N_EDGES 1600000
#define EPT     4
#define N_GROUPS (N_EDGES / EPT)          // 400000 8-lane groups
#define TILE_M  128
#define N_TILES ((N_NODES + TILE_M - 1) / TILE_M)   // 782

// Scratch: per-node precomputed [u+b1 | v] in fp16, 128 halves = 256 B/node
__device__ __half g_UVh[(size_t)N_NODES * 128];
// 1 if edge_index is int64 on device, 0 if int32.
__device__ int g_idx_is_64;

// ---- kernel-1 smem: B tile (fp16), 272B row stride (conflict-free)
#define ROW_BYTES 272
#define SMEM_K1 (128 * ROW_BYTES)          // 34816 B

__device__ __forceinline__ void mma_f16(float* d, uint32_t a0, uint32_t a1,
                                        uint32_t a2, uint32_t a3,
                                        uint32_t b0, uint32_t b1) {
    asm volatile(
        "mma.sync.aligned.m16n8k16.row.col.f32.f16.f16.f32 "
        "{%0,%1,%2,%3}, {%4,%5,%6,%7}, {%8,%9}, {%0,%1,%2,%3};"
        : "+f"(d[0]), "+f"(d[1]), "+f"(d[2]), "+f"(d[3])
        : "r"(a0), "r"(a1), "r"(a2), "r"(a3), "r"(b0), "r"(b1));
}

__device__ __forceinline__ uint32_t h2_pack(float x0, float x1) {
    __half2 h = __floats2half2_rn(x0, x1);
    return *(uint32_t*)&h;
}

// ---------------------------------------------------------------------------
// Kernel 1 (warp-MMA v5): UV[m][n] = sum_k emb[m][k]*Wc[k][n] (+b1[n], n<64)
//   Wc[k][n] = W1[k][n] (n<64) | W1[128+k][n-64] (n>=64)
// Single-pass fp16 MMA (A and B both fp16-rounded, fp32 accumulate).
// Combined error (A-GEMM + B-GEMM + fp16 store) ~5e-4 < 1e-3 threshold.
// 8 warps/CTA; warp w -> rows [16w,16w+16). A streamed gmem->regs per k-step.
// B (transposed Wt[n][k], fp16) staged once in smem, coalesced LDG.
// Fragment maps identical to the R7-verified ones. Block 0 detects eidx dtype.
// ---------------------------------------------------------------------------
__global__ __launch_bounds__(256, 2)
void precompute_uv_mma(const float* __restrict__ emb,
                       const float* __restrict__ W1,
                       const float* __restrict__ b1,
                       const int* __restrict__ eidx32) {
    extern __shared__ char smem[];
    int tid = threadIdx.x;

    __shared__ int s_any;
    if (blockIdx.x == 0) {
        if (tid == 0) s_any = 0;
        __syncthreads();
        if (tid < 128) {
            int w = eidx32[2 * (tid * 37 + 1) + 1];
            if (w != 0) atomicOr(&s_any, 1);
        }
        __syncthreads();
        if (tid == 0) g_idx_is_64 = (s_any == 0) ? 1 : 0;
    }

    // --- stage B (fp16): coalesced float2 LDG of W1 [256,64], transposed STS
    //   W1 row r, col c -> Wt[n=c+64*(r>=128)][k=r%128]
    for (int i = tid; i < 128 * 64; i += 256) {
        float2 x = *(const float2*)(W1 + 2 * (size_t)i);
        int r = (2 * i) >> 6;
        int c = (2 * i) & 63;
        int k = r & 127;
        int n = c + ((r >> 7) << 6);
        char* bh = smem + n * ROW_BYTES + k * 2;
        *(__half*)(bh)             = __float2half_rn(x.x);
        *(__half*)(bh + ROW_BYTES) = __float2half_rn(x.y);   // n+1, same k
    }
    __syncthreads();

    int wid = tid >> 5, lane = tid & 31;
    int g = lane >> 2, t = lane & 3;
    int base = blockIdx.x * TILE_M;
    int m0 = wid * 16;

    // clamped row indices for A loads (stores are guarded)
    int rowA = base + m0 + g;       if (rowA >= N_NODES) rowA = N_NODES - 1;
    int rowB = base + m0 + 8 + g;   if (rowB >= N_NODES) rowB = N_NODES - 1;
    const float* embA = emb + (size_t)rowA * EMB_DIM + 2 * t;
    const float* embB = emb + (size_t)rowB * EMB_DIM + 2 * t;

    // accumulators: 16 n-tiles x 4; init with b1 (cols < 64 only)
    float acc[16][4];
    #pragma unroll
    for (int nt = 0; nt < 16; nt++) {
        int col = 8 * nt + 2 * t;
        if (col < 64) {
            float2 b = *(const float2*)(b1 + col);
            acc[nt][0] = b.x; acc[nt][1] = b.y;
            acc[nt][2] = b.x; acc[nt][3] = b.y;
        } else {
            acc[nt][0] = acc[nt][1] = acc[nt][2] = acc[nt][3] = 0.f;
        }
    }

    const char* BH = smem;
    int brow = g * ROW_BYTES;

    #pragma unroll
    for (int ks = 0; ks < 8; ks++) {
        int k0 = ks * 16;
        // A fragments (verified map):
        //  a0={A[g][k0+2t..+1]} a1={A[8+g][..]} a2={A[g][k0+2t+8..]} a3={A[8+g][+8]}
        float2 xa0 = *(const float2*)(embA + k0);
        float2 xa1 = *(const float2*)(embB + k0);
        float2 xa2 = *(const float2*)(embA + k0 + 8);
        float2 xa3 = *(const float2*)(embB + k0 + 8);
        uint32_t a0 = h2_pack(xa0.x, xa0.y);
        uint32_t a1 = h2_pack(xa1.x, xa1.y);
        uint32_t a2 = h2_pack(xa2.x, xa2.y);
        uint32_t a3 = h2_pack(xa3.x, xa3.y);

        int kb0 = (k0 + 2 * t) * 2;
        int kb1 = (k0 + 2 * t + 8) * 2;
        #pragma unroll
        for (int nt = 0; nt < 16; nt++) {
            int roff = nt * 8 * ROW_BYTES + brow;
            uint32_t bh0 = *(const uint32_t*)(BH + roff + kb0);
            uint32_t bh1 = *(const uint32_t*)(BH + roff + kb1);
            mma_f16(acc[nt], a0, a1, a2, a3, bh0, bh1);
        }
    }

    // --- epilogue: fp16 store. lane owns D[g][2t..+1], D[8+g][2t..+1] per nt
    int node0 = base + m0 + g;
    int node1 = base + m0 + 8 + g;
    #pragma unroll
    for (int nt = 0; nt < 16; nt++) {
        int col = 8 * nt + 2 * t;
        if (node0 < N_NODES) {
            __half2 h = __floats2half2_rn(acc[nt][0], acc[nt][1]);
            *(__half2*)(g_UVh + (size_t)node0 * 128 + col) = h;
        }
        if (node1 < N_NODES) {
            __half2 h = __floats2half2_rn(acc[nt][2], acc[nt][3]);
            *(__half2*)(g_UVh + (size_t)node1 * 128 + col) = h;
        }
    }
}

// ---------------------------------------------------------------------------
// Kernel 2: per-edge score (unchanged R11/R12 winner, at its L2-byte floor).
// 8 lanes per edge, 4 edges per thread; each gather = one 128B line.
// ---------------------------------------------------------------------------
__global__ __launch_bounds__(256)
void edge_score_kernel(const int* __restrict__ eidx32,
                       const float* __restrict__ W2,
                       const float* __restrict__ b2,
                       float* __restrict__ out) {
    int gtid = blockIdx.x * blockDim.x + threadIdx.x;
    int group = gtid >> 3;
    if (group >= N_GROUPS) return;
    int s = gtid & 7;

    int stride = g_idx_is_64 ? 2 : 1;

    float4 w0 = *(const float4*)(W2 + s * 8);
    float4 w1 = *(const float4*)(W2 + s * 8 + 4);
    float bias2 = b2[0];
    __half2 zero2 = __floats2half2_rn(0.f, 0.f);

    int src[EPT], tgt[EPT];
    #pragma unroll
    for (int j = 0; j < EPT; j++) {
        int e = group + j * N_GROUPS;
        src[j] = eidx32[(size_t)e * stride];
        tgt[j] = eidx32[((size_t)(N_EDGES + e)) * stride];
    }

    uint4 uraw[EPT], vraw[EPT];
    #pragma unroll
    for (int j = 0; j < EPT; j++) {
        uraw[j] = *(const uint4*)(g_UVh + (size_t)src[j] * 128 + s * 8);
        vraw[j] = *(const uint4*)(g_UVh + (size_t)tgt[j] * 128 + 64 + s * 8);
    }

    #pragma unroll
    for (int j = 0; j < EPT; j++) {
        const __half2* u = (const __half2*)&uraw[j];
        const __half2* v = (const __half2*)&vraw[j];

        __half2 z0 = __hmax2(__hadd2(u[0], v[0]), zero2);
        __half2 z1 = __hmax2(__hadd2(u[1], v[1]), zero2);
        __half2 z2 = __hmax2(__hadd2(u[2], v[2]), zero2);
        __half2 z3 = __hmax2(__hadd2(u[3], v[3]), zero2);

        float2 f0 = __half22float2(z0);
        float2 f1 = __half22float2(z1);
        float2 f2 = __half22float2(z2);
        float2 f3 = __half22float2(z3);

        float p;
        p = f0.x * w0.x;
        p = fmaf(f0.y, w0.y, p);
        p = fmaf(f1.x, w0.z, p);
        p = fmaf(f1.y, w0.w, p);
        p = fmaf(f2.x, w1.x, p);
        p = fmaf(f2.y, w1.y, p);
        p = fmaf(f3.x, w1.z, p);
        p = fmaf(f3.y, w1.w, p);

        p += __shfl_xor_sync(0xFFFFFFFFu, p, 4);
        p += __shfl_xor_sync(0xFFFFFFFFu, p, 2);
        p += __shfl_xor_sync(0xFFFFFFFFu, p, 1);

        if (s == 0) out[group + j * N_GROUPS] = p + bias2;
    }
}

// ---------------------------------------------------------------------------
extern "C" void kernel_launch(void* const* d_in, const int* in_sizes, int n_in,
                              void* d_out, int out_size) {
    const float* emb  = (const float*)d_in[0];
    const void*  eidx = d_in[1];
    const float* W1   = (const float*)d_in[2];
    const float* b1   = (const float*)d_in[3];
    const float* W2   = (const float*)d_in[4];
    const float* b2   = (const float*)d_in[5];
    float*       out  = (float*)d_out;

    // Kernel 1: 782 CTAs x 256 threads, 34.8KB smem
    precompute_uv_mma<<<N_TILES, 256, SMEM_K1>>>(emb, W1, b1, (const int*)eidx);

    // Kernel 2: 8 threads per 4 edges -> 12500 blocks
    {
        int blocks = (N_GROUPS * 8 + 255) / 256;
        edge_score_kernel<<<blocks, 256>>>((const int*)eidx, W2, b2, out);
    }
}

// round 17
// speedup vs baseline: 3.5869x; 1.0391x over previous
#include <cuda_runtime.h>
#include <cuda_bf16.h>
#include <cuda_fp16.h>
#include <cstdint>

#define N_NODES 100000
#define EMB_DIM 128
#define HIDDEN  64
#define N_EDGES 1600000
#define EPT     4
#define N_GROUPS (N_EDGES / EPT)          // 400000 8-lane groups
#define TILE_M  128
#define N_TILES ((N_NODES + TILE_M - 1) / TILE_M)   // 782

// Scratch: per-node precomputed [u+b1 | v] in fp16, 128 halves = 256 B/node
__device__ __half g_UVh[(size_t)N_NODES * 128];
// 1 if edge_index is int64 on device, 0 if int32.
__device__ int g_idx_is_64;

// ---- kernel-1 smem: B tile (fp16), 272B row stride; reused as D buffer
// 272 = 17*16 -> every row 16B-aligned (uint4-safe), 4-bank skew per row.
#define ROW_BYTES 272
#define D_ROW_BYTES 272
#define SMEM_K1 (128 * ROW_BYTES)          // 34816 B

__device__ __forceinline__ void mma_f16(float* d, uint32_t a0, uint32_t a1,
                                        uint32_t a2, uint32_t a3,
                                        uint32_t b0, uint32_t b1) {
    asm volatile(
        "mma.sync.aligned.m16n8k16.row.col.f32.f16.f16.f32 "
        "{%0,%1,%2,%3}, {%4,%5,%6,%7}, {%8,%9}, {%0,%1,%2,%3};"
        : "+f"(d[0]), "+f"(d[1]), "+f"(d[2]), "+f"(d[3])
        : "r"(a0), "r"(a1), "r"(a2), "r"(a3), "r"(b0), "r"(b1));
}

__device__ __forceinline__ uint32_t h2_pack(float x0, float x1) {
    __half2 h = __floats2half2_rn(x0, x1);
    return *(uint32_t*)&h;
}

// ---------------------------------------------------------------------------
// Kernel 1 (warp-MMA v6b): UV[m][n] = sum_k emb[m][k]*Wc[k][n] (+b1[n], n<64)
//   Wc[k][n] = W1[k][n] (n<64) | W1[128+k][n-64] (n>=64)
// Single-pass fp16 MMA (fp32 accumulate). 8 warps/CTA, warp w -> rows
// [16w,16w+16). A streamed gmem->regs; B (transposed fp16) staged in smem.
// Epilogue stages D in smem (reusing the B tile, 16B-aligned rows) and
// stores to gmem as fully-coalesced 16B chunks. Block 0 detects eidx dtype.
// ---------------------------------------------------------------------------
__global__ __launch_bounds__(256, 2)
void precompute_uv_mma(const float* __restrict__ emb,
                       const float* __restrict__ W1,
                       const float* __restrict__ b1,
                       const int* __restrict__ eidx32) {
    extern __shared__ char smem[];
    int tid = threadIdx.x;

    __shared__ int s_any;
    if (blockIdx.x == 0) {
        if (tid == 0) s_any = 0;
        __syncthreads();
        if (tid < 128) {
            int w = eidx32[2 * (tid * 37 + 1) + 1];
            if (w != 0) atomicOr(&s_any, 1);
        }
        __syncthreads();
        if (tid == 0) g_idx_is_64 = (s_any == 0) ? 1 : 0;
    }

    // --- stage B (fp16): coalesced float2 LDG of W1 [256,64], transposed STS
    //   W1 row r, col c -> Wt[n=c+64*(r>=128)][k=r%128]
    for (int i = tid; i < 128 * 64; i += 256) {
        float2 x = *(const float2*)(W1 + 2 * (size_t)i);
        int r = (2 * i) >> 6;
        int c = (2 * i) & 63;
        int k = r & 127;
        int n = c + ((r >> 7) << 6);
        char* bh = smem + n * ROW_BYTES + k * 2;
        *(__half*)(bh)             = __float2half_rn(x.x);
        *(__half*)(bh + ROW_BYTES) = __float2half_rn(x.y);   // n+1, same k
    }
    __syncthreads();

    int wid = tid >> 5, lane = tid & 31;
    int g = lane >> 2, t = lane & 3;
    int base = blockIdx.x * TILE_M;
    int m0 = wid * 16;

    // clamped row indices for A loads (output rows are guarded in the copy)
    int rowA = base + m0 + g;       if (rowA >= N_NODES) rowA = N_NODES - 1;
    int rowB = base + m0 + 8 + g;   if (rowB >= N_NODES) rowB = N_NODES - 1;
    const float* embA = emb + (size_t)rowA * EMB_DIM + 2 * t;
    const float* embB = emb + (size_t)rowB * EMB_DIM + 2 * t;

    // accumulators: 16 n-tiles x 4; init with b1 (cols < 64 only)
    float acc[16][4];
    #pragma unroll
    for (int nt = 0; nt < 16; nt++) {
        int col = 8 * nt + 2 * t;
        if (col < 64) {
            float2 b = *(const float2*)(b1 + col);
            acc[nt][0] = b.x; acc[nt][1] = b.y;
            acc[nt][2] = b.x; acc[nt][3] = b.y;
        } else {
            acc[nt][0] = acc[nt][1] = acc[nt][2] = acc[nt][3] = 0.f;
        }
    }

    const char* BH = smem;
    int brow = g * ROW_BYTES;

    #pragma unroll
    for (int ks = 0; ks < 8; ks++) {
        int k0 = ks * 16;
        float2 xa0 = *(const float2*)(embA + k0);
        float2 xa1 = *(const float2*)(embB + k0);
        float2 xa2 = *(const float2*)(embA + k0 + 8);
        float2 xa3 = *(const float2*)(embB + k0 + 8);
        uint32_t a0 = h2_pack(xa0.x, xa0.y);
        uint32_t a1 = h2_pack(xa1.x, xa1.y);
        uint32_t a2 = h2_pack(xa2.x, xa2.y);
        uint32_t a3 = h2_pack(xa3.x, xa3.y);

        int kb0 = (k0 + 2 * t) * 2;
        int kb1 = (k0 + 2 * t + 8) * 2;
        #pragma unroll
        for (int nt = 0; nt < 16; nt++) {
            int roff = nt * 8 * ROW_BYTES + brow;
            uint32_t bh0 = *(const uint32_t*)(BH + roff + kb0);
            uint32_t bh1 = *(const uint32_t*)(BH + roff + kb1);
            mma_f16(acc[nt], a0, a1, a2, a3, bh0, bh1);
        }
    }

    // --- epilogue: scatter D into smem (B tile no longer needed), then
    //     copy out with fully-coalesced 16B chunks.
    __syncthreads();   // all B reads done before overwrite

    #pragma unroll
    for (int nt = 0; nt < 16; nt++) {
        int col = 8 * nt + 2 * t;
        __half2 h0 = __floats2half2_rn(acc[nt][0], acc[nt][1]);
        __half2 h1 = __floats2half2_rn(acc[nt][2], acc[nt][3]);
        *(__half2*)(smem + (m0 + g)     * D_ROW_BYTES + col * 2) = h0;
        *(__half2*)(smem + (m0 + 8 + g) * D_ROW_BYTES + col * 2) = h1;
    }
    __syncthreads();

    // copy: 128 rows x 256 B = 2048 chunks of 16 B; 8 chunks per thread
    #pragma unroll
    for (int i = 0; i < 8; i++) {
        int c = tid + i * 256;
        int row = c >> 4;
        int off = (c & 15) * 16;
        int node = base + row;
        if (node < N_NODES) {
            uint4 v = *(const uint4*)(smem + row * D_ROW_BYTES + off);
            *(uint4*)((char*)(g_UVh + (size_t)node * 128) + off) = v;
        }
    }
}

// ---------------------------------------------------------------------------
// Kernel 2: per-edge score (unchanged R11/R12 winner, at its L2-byte floor).
// 8 lanes per edge, 4 edges per thread; each gather = one 128B line.
// ---------------------------------------------------------------------------
__global__ __launch_bounds__(256)
void edge_score_kernel(const int* __restrict__ eidx32,
                       const float* __restrict__ W2,
                       const float* __restrict__ b2,
                       float* __restrict__ out) {
    int gtid = blockIdx.x * blockDim.x + threadIdx.x;
    int group = gtid >> 3;
    if (group >= N_GROUPS) return;
    int s = gtid & 7;

    int stride = g_idx_is_64 ? 2 : 1;

    float4 w0 = *(const float4*)(W2 + s * 8);
    float4 w1 = *(const float4*)(W2 + s * 8 + 4);
    float bias2 = b2[0];
    __half2 zero2 = __floats2half2_rn(0.f, 0.f);

    int src[EPT], tgt[EPT];
    #pragma unroll
    for (int j = 0; j < EPT; j++) {
        int e = group + j * N_GROUPS;
        src[j] = eidx32[(size_t)e * stride];
        tgt[j] = eidx32[((size_t)(N_EDGES + e)) * stride];
    }

    uint4 uraw[EPT], vraw[EPT];
    #pragma unroll
    for (int j = 0; j < EPT; j++) {
        uraw[j] = *(const uint4*)(g_UVh + (size_t)src[j] * 128 + s * 8);
        vraw[j] = *(const uint4*)(g_UVh + (size_t)tgt[j] * 128 + 64 + s * 8);
    }

    #pragma unroll
    for (int j = 0; j < EPT; j++) {
        const __half2* u = (const __half2*)&uraw[j];
        const __half2* v = (const __half2*)&vraw[j];

        __half2 z0 = __hmax2(__hadd2(u[0], v[0]), zero2);
        __half2 z1 = __hmax2(__hadd2(u[1], v[1]), zero2);
        __half2 z2 = __hmax2(__hadd2(u[2], v[2]), zero2);
        __half2 z3 = __hmax2(__hadd2(u[3], v[3]), zero2);

        float2 f0 = __half22float2(z0);
        float2 f1 = __half22float2(z1);
        float2 f2 = __half22float2(z2);
        float2 f3 = __half22float2(z3);

        float p;
        p = f0.x * w0.x;
        p = fmaf(f0.y, w0.y, p);
        p = fmaf(f1.x, w0.z, p);
        p = fmaf(f1.y, w0.w, p);
        p = fmaf(f2.x, w1.x, p);
        p = fmaf(f2.y, w1.y, p);
        p = fmaf(f3.x, w1.z, p);
        p = fmaf(f3.y, w1.w, p);

        p += __shfl_xor_sync(0xFFFFFFFFu, p, 4);
        p += __shfl_xor_sync(0xFFFFFFFFu, p, 2);
        p += __shfl_xor_sync(0xFFFFFFFFu, p, 1);

        if (s == 0) out[group + j * N_GROUPS] = p + bias2;
    }
}

// ---------------------------------------------------------------------------
extern "C" void kernel_launch(void* const* d_in, const int* in_sizes, int n_in,
                              void* d_out, int out_size) {
    const float* emb  = (const float*)d_in[0];
    const void*  eidx = d_in[1];
    const float* W1   = (const float*)d_in[2];
    const float* b1   = (const float*)d_in[3];
    const float* W2   = (const float*)d_in[4];
    const float* b2   = (const float*)d_in[5];
    float*       out  = (float*)d_out;

    // Kernel 1: 782 CTAs x 256 threads, 34.8KB smem
    precompute_uv_mma<<<N_TILES, 256, SMEM_K1>>>(emb, W1, b1, (const int*)eidx);

    // Kernel 2: 8 threads per 4 edges -> 12500 blocks
    {
        int blocks = (N_GROUPS * 8 + 255) / 256;
        edge_score_kernel<<<blocks, 256>>>((const int*)eidx, W2, b2, out);
    }
}